// round 2
// baseline (speedup 1.0000x reference)
#include <cuda_runtime.h>
#include <math.h>

#define BB 8
#define NN 2048
#define FF 64
#define ALPHA_ 0.2f
#define NCH 130          // 64 (e^y * Wh) + 64 (e^{ay} * Wh) + e^y + e^{ay}
#define KP 2064          // padded prefix stride (>= NN+1)

// ---- scratch (static device globals; no allocations) ----
__device__ float g_Wh[BB*NN*FF];       // 4 MB
__device__ float g_ssrc[BB*NN];
__device__ float g_sdst[BB*NN];
__device__ float g_ysort[BB*NN];
__device__ int   g_perm[BB*NN];
__device__ float g_pref[BB*NCH*KP];    // ~8.6 MB, L2 resident
__device__ float g_tot[BB*NCH];

// ============================================================
// K1: Wh = h @ W ; s_src = Wh @ a[:64] ; s_dst = Wh @ a[64:]
// block = 256 thr = 4 rows x 64 f, 8 iterations -> 32 rows/block
// ============================================================
__global__ __launch_bounds__(256) void k_wh(const float* __restrict__ h,
                                            const float* __restrict__ Wm,
                                            const float* __restrict__ av) {
    __shared__ float sW[FF*FF];
    __shared__ float sh[4][FF];
    __shared__ float sred[4][2][2];   // [row][src/dst][warp-half]
    int tid = threadIdx.x;
    for (int i = tid; i < FF*FF; i += 256) sW[i] = Wm[i];
    int r = tid >> 6, f = tid & 63;
    float asrc = av[f], adst = av[FF + f];
    int rowBase = blockIdx.x * 32;

    for (int it = 0; it < 8; ++it) {
        int row = rowBase + it * 4 + r;          // global row in [0, B*N)
        __syncthreads();                         // protect sh/sred reuse
        sh[r][f] = h[row*FF + f];
        __syncthreads();
        float acc = 0.f;
        #pragma unroll
        for (int kk = 0; kk < FF; ++kk) acc += sh[r][kk] * sW[kk*FF + f];
        g_Wh[row*FF + f] = acc;
        float ts = acc * asrc, td = acc * adst;
        #pragma unroll
        for (int o = 16; o > 0; o >>= 1) {
            ts += __shfl_down_sync(0xffffffffu, ts, o);
            td += __shfl_down_sync(0xffffffffu, td, o);
        }
        if ((f & 31) == 0) { sred[r][0][f >> 5] = ts; sred[r][1][f >> 5] = td; }
        __syncthreads();
        if (f == 0) {
            g_ssrc[row] = sred[r][0][0] + sred[r][0][1];
            g_sdst[row] = sred[r][1][0] + sred[r][1][1];
        }
    }
}

// ============================================================
// K2: per-batch bitonic sort of (y = s_dst, idx), ascending
// one block of 1024 threads sorts 2048 elements in shared
// ============================================================
__global__ __launch_bounds__(1024) void k_sort() {
    __shared__ float sk[NN];
    __shared__ int   sv[NN];
    int b = blockIdx.x, tid = threadIdx.x;
    for (int i = tid; i < NN; i += 1024) { sk[i] = g_sdst[b*NN + i]; sv[i] = i; }
    for (int size = 2; size <= NN; size <<= 1) {
        bool ddd = ((tid & (size >> 1)) == 0);   // dir=1 (ascending) ^ bit
        for (int stride = size >> 1; stride > 0; stride >>= 1) {
            __syncthreads();
            int pos = 2*tid - (tid & (stride - 1));
            float ka = sk[pos], kb = sk[pos + stride];
            if ((ka > kb) == ddd) {
                sk[pos] = kb; sk[pos + stride] = ka;
                int va = sv[pos]; sv[pos] = sv[pos + stride]; sv[pos + stride] = va;
            }
        }
    }
    __syncthreads();
    for (int i = tid; i < NN; i += 1024) { g_ysort[b*NN + i] = sk[i]; g_perm[b*NN + i] = sv[i]; }
}

// ============================================================
// K3: inclusive prefix sums along sorted order, per (batch, channel)
// ch 0..63  : e^{y} * Wh[perm, f]
// ch 64..127: e^{a y} * Wh[perm, f]
// ch 128    : e^{y}        ch 129: e^{a y}
// 256 threads, 8 elements/thread, warp-shuffle block scan
// ============================================================
__global__ __launch_bounds__(256) void k_scan() {
    int ch = blockIdx.x;            // 0..129
    int b  = blockIdx.y;
    int tid = threadIdx.x;
    bool alpha  = (ch >= FF && ch < 2*FF) || (ch == 129);
    bool scalar = (ch >= 2*FF);
    int f = ch & 63;
    float scale = alpha ? ALPHA_ : 1.0f;

    const float* ys = &g_ysort[b*NN];
    const int*   pm = &g_perm[b*NN];
    float loc[8];
    float run = 0.f;
    int base = tid * 8;
    #pragma unroll
    for (int u = 0; u < 8; ++u) {
        int k = base + u;
        float w = expf(scale * ys[k]);
        float v = scalar ? w : w * g_Wh[(b*NN + pm[k])*FF + f];
        run += v;
        loc[u] = run;
    }
    // block inclusive scan of per-thread totals
    int lane = tid & 31, wid = tid >> 5;
    float v = run;
    #pragma unroll
    for (int o = 1; o < 32; o <<= 1) {
        float nv = __shfl_up_sync(0xffffffffu, v, o);
        if (lane >= o) v += nv;
    }
    __shared__ float wsum[8];
    if (lane == 31) wsum[wid] = v;
    __syncthreads();
    float woff = 0.f;
    for (int i = 0; i < wid; ++i) woff += wsum[i];
    float excl = woff + v - run;    // exclusive offset for this thread

    float* P = &g_pref[(b*NCH + ch)*KP];
    #pragma unroll
    for (int u = 0; u < 8; ++u) P[1 + base + u] = excl + loc[u];
    if (tid == 0)   P[0] = 0.f;
    if (tid == 255) g_tot[b*NCH + ch] = excl + loc[7];
}

// ============================================================
// K4: output. Per row i: k = #{ y_j <= -c_i } (binary search in shared),
// combine prefix/suffix of the two weighted sums, normalize, ELU.
// block = 512 thr = 8 rows x 64 f
// ============================================================
__global__ __launch_bounds__(512) void k_out(float* __restrict__ out) {
    int b    = blockIdx.y;
    int row0 = blockIdx.x * 8;
    int tid  = threadIdx.x;
    int r = tid >> 6, f = tid & 63;
    __shared__ float sy[NN];
    __shared__ int   skk[8];
    __shared__ float sec[8], seac[8];
    for (int i = tid; i < NN; i += 512) sy[i] = g_ysort[b*NN + i];
    __syncthreads();
    if (f == 0) {
        float c = g_ssrc[b*NN + row0 + r];
        float t = -c;
        int lo = 0, hi = NN;                      // first idx with sy[idx] > t
        while (lo < hi) { int mid = (lo + hi) >> 1; if (sy[mid] > t) hi = mid; else lo = mid + 1; }
        skk[r]  = lo;
        sec[r]  = expf(c);
        seac[r] = expf(ALPHA_ * c);
    }
    __syncthreads();
    int k = skk[r];
    float ec = sec[r], eac = seac[r];
    const float* Pb = &g_pref[b*NCH*KP];
    float Pp  = Pb[f*KP + k];                 // prefix of e^{y} Wh
    float Pn  = Pb[(FF + f)*KP + k];          // prefix of e^{a y} Wh
    float Tp  = g_tot[b*NCH + f];
    float Pz  = Pb[128*KP + k];
    float Pza = Pb[129*KP + k];
    float Tz  = g_tot[b*NCH + 128];
    float num = ec * (Tp - Pp) + eac * Pn;
    float den = ec * (Tz - Pz) + eac * Pza;
    float vv = num / den;
    out[(b*NN + row0 + r)*FF + f] = vv > 0.f ? vv : expm1f(vv);
}

// ============================================================
extern "C" void kernel_launch(void* const* d_in, const int* in_sizes, int n_in,
                              void* d_out, int /*out_size*/) {
    const float *h = nullptr, *Wm = nullptr, *av = nullptr;
    for (int i = 0; i < n_in; ++i) {
        if      (in_sizes[i] == BB*NN*FF) h  = (const float*)d_in[i];
        else if (in_sizes[i] == FF*FF)    Wm = (const float*)d_in[i];
        else if (in_sizes[i] == 2*FF)     av = (const float*)d_in[i];
    }
    k_wh  <<<(BB*NN)/32, 256>>>(h, Wm, av);
    k_sort<<<BB, 1024>>>();
    k_scan<<<dim3(NCH, BB), 256>>>();
    k_out <<<dim3(NN/8, BB), 512>>>((float*)d_out);
}